// round 13
// baseline (speedup 1.0000x reference)
#include <cuda_runtime.h>
#include <cuda_fp16.h>
#include <cstdint>
#include <cstddef>

#define N_CLASS 8192
#define FEAT    1024
#define BATCH   1024

#define TM 128
#define TN 128
#define TK 64
#define KTILES (FEAT / TK)        // 16
#define A_BYTES (TM * 128)        // 16 KB (128 rows x 128B)
#define B_BYTES (TN * 128)        // 16 KB
#define STAGE_BYTES (A_BYTES + B_BYTES)   // 32 KB
#define CTRL_OFF (2 * STAGE_BYTES)        // 64 KB
#define SMEM_TOTAL (CTRL_OFF + 64 + 1024) // + barriers + srow/scol

#define NTILE (N_CLASS / TM)                  // 64
#define NTRI  (NTILE * (NTILE + 1) / 2)       // 2080 upper-triangle tiles
#define PCTAS 456                             // 3 CTAs/SM x 152 SMs (persistent)
#define CAP 32

// ---------------- device scratch (no allocations allowed) ----------------
__device__ __half g_protos[(size_t)N_CLASS * FEAT];  // 16 MB fp16 protos
__device__ float  g_rowsum[N_CLASS];
__device__ int    g_done;

// ---------------- helpers ----------------
__device__ __forceinline__ uint32_t smem_u32(const void* p) {
    uint32_t a;
    asm("{ .reg .u64 t; cvta.to.shared.u64 t, %1; cvt.u32.u64 %0, t; }" : "=r"(a) : "l"(p));
    return a;
}
__device__ __forceinline__ void ldmatrix_x4(uint32_t& r0, uint32_t& r1,
                                            uint32_t& r2, uint32_t& r3, uint32_t addr) {
    asm volatile("ldmatrix.sync.aligned.m8n8.x4.shared.b16 {%0,%1,%2,%3}, [%4];"
                 : "=r"(r0), "=r"(r1), "=r"(r2), "=r"(r3) : "r"(addr));
}
__device__ __forceinline__ void mma_f16acc(uint32_t& c0, uint32_t& c1,
                                           uint32_t a0, uint32_t a1, uint32_t a2, uint32_t a3,
                                           uint32_t b0, uint32_t b1) {
    asm volatile(
        "mma.sync.aligned.m16n8k16.row.col.f16.f16.f16.f16 "
        "{%0,%1}, {%2,%3,%4,%5}, {%6,%7}, {%0,%1};"
        : "+r"(c0), "+r"(c1)
        : "r"(a0), "r"(a1), "r"(a2), "r"(a3), "r"(b0), "r"(b1));
}
__device__ __forceinline__ void mbar_init(uint32_t mbar, uint32_t cnt) {
    asm volatile("mbarrier.init.shared.b64 [%0], %1;" :: "r"(mbar), "r"(cnt) : "memory");
}
__device__ __forceinline__ void mbar_arrive(uint32_t mbar) {
    asm volatile("mbarrier.arrive.shared.b64 _, [%0];" :: "r"(mbar) : "memory");
}
__device__ __forceinline__ void cpasync_arrive(uint32_t mbar) {
    asm volatile("cp.async.mbarrier.arrive.noinc.shared.b64 [%0];" :: "r"(mbar) : "memory");
}
__device__ __forceinline__ void mbar_wait(uint32_t mbar, uint32_t parity) {
    asm volatile(
        "{\n\t.reg .pred P;\n\t"
        "W_%=:\n\t"
        "mbarrier.try_wait.parity.acquire.cta.shared::cta.b64 P, [%0], %1, 0x989680;\n\t"
        "@!P bra W_%=;\n\t}"
        :: "r"(mbar), "r"(parity) : "memory");
}
__device__ __forceinline__ void tile_decode(int id, int& ti, int& tj) {
    int a = (int)((2.0f * NTILE + 1.0f
                   - sqrtf((2.0f * NTILE + 1.0f) * (2.0f * NTILE + 1.0f) - 8.0f * id))
                  * 0.5f);
    while ((a + 1) * NTILE - ((a + 1) * a) / 2 <= id) a++;
    while (a * NTILE - (a * (a - 1)) / 2 > id) a--;
    ti = a;
    tj = a + (id - (a * NTILE - (a * (a - 1)) / 2));
}

// ============================================================================
// Kernel 1: fused label-scan + EMA + fp32->fp16 convert (one block per class)
// ============================================================================
__global__ void __launch_bounds__(256) ema_convert_kernel(
    const float* __restrict__ protos,
    const float* __restrict__ feats,
    const int*   __restrict__ labels)
{
    const int c = blockIdx.x;
    const int t = threadIdx.x;

    __shared__ int   s_cnt;
    __shared__ int   s_idx[CAP];
    __shared__ float s_red[8];

    if (t == 0) s_cnt = 0;
    __syncthreads();

    #pragma unroll
    for (int i = t; i < BATCH; i += 256) {
        if (labels[i] == c) {
            int p = atomicAdd(&s_cnt, 1);
            if (p < CAP) s_idx[p] = i;
        }
    }
    __syncthreads();

    float4 r = reinterpret_cast<const float4*>(protos)[(size_t)c * (FEAT / 4) + t];

    const int cnt = min(s_cnt, CAP);
    if (cnt > 0) {
        if (t == 0) {  // order matters: insertion-sort the (tiny) match list
            for (int a = 1; a < cnt; a++) {
                int v = s_idx[a], b = a - 1;
                while (b >= 0 && s_idx[b] > v) { s_idx[b + 1] = s_idx[b]; b--; }
                s_idx[b + 1] = v;
            }
        }
        __syncthreads();
        for (int m = 0; m < cnt; m++) {
            const int i = s_idx[m];
            float4 f = reinterpret_cast<const float4*>(feats)[(size_t)i * (FEAT / 4) + t];
            r.x = r.x * 0.95f + 0.05f * f.x;
            r.y = r.y * 0.95f + 0.05f * f.y;
            r.z = r.z * 0.95f + 0.05f * f.z;
            r.w = r.w * 0.95f + 0.05f * f.w;
            float ss = r.x * r.x + r.y * r.y + r.z * r.z + r.w * r.w;
            #pragma unroll
            for (int o = 16; o > 0; o >>= 1) ss += __shfl_xor_sync(0xffffffffu, ss, o);
            if ((t & 31) == 0) s_red[t >> 5] = ss;
            __syncthreads();
            float tot = s_red[0] + s_red[1] + s_red[2] + s_red[3]
                      + s_red[4] + s_red[5] + s_red[6] + s_red[7];
            float inv = 1.0f / fmaxf(sqrtf(tot), 1e-12f);
            r.x *= inv; r.y *= inv; r.z *= inv; r.w *= inv;
            __syncthreads();
        }
    }

    __half2* dst = reinterpret_cast<__half2*>(g_protos + (size_t)c * FEAT + (size_t)t * 4);
    dst[0] = __floats2half2_rn(r.x, r.y);
    dst[1] = __floats2half2_rn(r.z, r.w);
    if (t == 0) {
        g_rowsum[c] = 0.0f;
        if (c == 0) g_done = 0;
    }
}

// ============================================================================
// Kernel 2: PERSISTENT fused symmetric Gram GEMM + exp + sums + finalize.
// 456 CTAs stride over 2080 tiles; cp.async pipeline stays full across tile
// boundaries (continuous-K parity); epilogue overlaps next tile's loads.
// ============================================================================
__global__ void __launch_bounds__(128, 3) gemm_exp_kernel(float* __restrict__ out)
{
    extern __shared__ __align__(1024) char smem[];
    const uint32_t sb   = smem_u32(smem);
    const uint32_t ctrl = sb + CTRL_OFF;   // wr[0],wr[1] at +0,+8 ; rd[0],rd[1] at +16,+24
    float* srow = reinterpret_cast<float*>(smem + CTRL_OFF + 64);   // [128]
    float* scol = srow + 128;                                       // [128]

    const int t   = threadIdx.x;          // 0..127
    const int wid = t >> 5;
    const int lid = t & 31;
    const int wr  = wid >> 1;
    const int wc  = wid & 1;

    const __half* __restrict__ P = g_protos;

    if (t == 0) {
        #pragma unroll
        for (int s = 0; s < 2; s++) { mbar_init(ctrl + s * 8, 128); mbar_init(ctrl + 16 + s * 8, 128); }
    }
    __syncthreads();

    // ---- per-thread loader constants ----
    const int kc = t & 7;
    const int r0 = t >> 3;
    const uint32_t dOffA = r0 * 128 + ((kc ^ (r0 & 7)) << 4);

    // slot loader: srcA/srcB already point at this k-tile's first chunk
    auto load_stage = [&](int slot, const __half* sA, const __half* sB) {
        const uint32_t dA = sb + slot * STAGE_BYTES + dOffA;
        #pragma unroll
        for (int q = 0; q < 8; q++) {
            asm volatile("cp.async.cg.shared.global [%0], [%1], 16;"
                         :: "r"(dA + q * 2048), "l"(sA + (size_t)q * 16 * FEAT));
            asm volatile("cp.async.cg.shared.global [%0], [%1], 16;"
                         :: "r"(dA + A_BYTES + q * 2048), "l"(sB + (size_t)q * 16 * FEAT));
        }
        cpasync_arrive(ctrl + slot * 8);
    };

    // ---- fragment machinery (identical to R12) ----
    uint32_t acc[4][8][2];
    #pragma unroll
    for (int mf = 0; mf < 4; mf++)
        #pragma unroll
        for (int nf = 0; nf < 8; nf++) { acc[mf][nf][0] = 0u; acc[mf][nf][1] = 0u; }

    const int lmod16 = lid & 15;
    const int ldiv16 = lid >> 4;
    const int xsw    = lmod16 & 7;
    uint32_t aOff[4], bOff[4];
    #pragma unroll
    for (int mf = 0; mf < 4; mf++) aOff[mf] = (wr * 64 + mf * 16 + lmod16) * 128;
    #pragma unroll
    for (int np = 0; np < 4; np++) bOff[np] = (wc * 64 + np * 16 + lmod16) * 128;

    uint32_t a[2][4][4];
    uint32_t b[2][8][2];

    auto ldfrag = [&](int buf, int slot, int ks) {
        const uint32_t base = sb + slot * STAGE_BYTES;
        const uint32_t sw = (uint32_t)(((ks * 2 + ldiv16) ^ xsw) << 4);
        #pragma unroll
        for (int mf = 0; mf < 4; mf++)
            ldmatrix_x4(a[buf][mf][0], a[buf][mf][1], a[buf][mf][2], a[buf][mf][3],
                        base + aOff[mf] + sw);
        #pragma unroll
        for (int np = 0; np < 4; np++) {
            uint32_t q0, q1, q2, q3;
            ldmatrix_x4(q0, q1, q2, q3, base + A_BYTES + bOff[np] + sw);
            b[buf][np * 2 + 0][0] = q0; b[buf][np * 2 + 0][1] = q2;
            b[buf][np * 2 + 1][0] = q1; b[buf][np * 2 + 1][1] = q3;
        }
    };

    auto mma_step = [&](int buf) {
        #pragma unroll
        for (int mf = 0; mf < 4; mf++)
            #pragma unroll
            for (int nf = 0; nf < 8; nf++)
                mma_f16acc(acc[mf][nf][0], acc[mf][nf][1],
                           a[buf][mf][0], a[buf][mf][1], a[buf][mf][2], a[buf][mf][3],
                           b[buf][nf][0], b[buf][nf][1]);
    };

    // ---- persistent tile loop ----
    const int G = gridDim.x;
    int tile = blockIdx.x;
    int ti, tj;
    tile_decode(tile, ti, tj);
    int rowBase = ti * TM;
    int colBase = tj * TN;
    const __half* pA0 = P + (size_t)(rowBase + r0) * FEAT + kc * 8;
    const __half* pB0 = P + (size_t)(colBase + r0) * FEAT + kc * 8;

    // prologue: K=0 -> slot0 (kt0), K=1 -> slot1 (kt1)
    load_stage(0, pA0, pB0);
    load_stage(1, pA0 + TK, pB0 + TK);

    int K = 0;
    mbar_wait(ctrl + 0, 0);       // first write of slot 0
    ldfrag(0, 0, 0);

    for (;;) {
        // precompute next tile (needed for cross-boundary loads at kt=14,15)
        const int ntile = tile + G;
        const bool hasNext = (ntile < NTRI);
        const __half* nA0 = pA0;
        const __half* nB0 = pB0;
        int nRow = rowBase, nCol = colBase;
        if (hasNext) {
            int nti, ntj;
            tile_decode(ntile, nti, ntj);
            nRow = nti * TM;
            nCol = ntj * TN;
            nA0 = P + (size_t)(nRow + r0) * FEAT + kc * 8;
            nB0 = P + (size_t)(nCol + r0) * FEAT + kc * 8;
        }
        const bool diag = (rowBase == colBase);

        for (int kt = 0; kt < KTILES; kt++, K++) {
            const int slot = K & 1;
            ldfrag(1, slot, 1);
            mma_step(0);
            ldfrag(0, slot, 2);
            mma_step(1);
            ldfrag(1, slot, 3);
            mbar_arrive(ctrl + 16 + slot * 8);          // done reading this slot
            mma_step(0);
            if (kt <= KTILES - 3 || hasNext) {
                mbar_wait(ctrl + 16 + slot * 8, (uint32_t)((K >> 1) & 1));  // all warps done
                if (kt <= KTILES - 3)
                    load_stage(slot, pA0 + (kt + 2) * TK, pB0 + (kt + 2) * TK);
                else
                    load_stage(slot, nA0 + (kt - 14) * TK, nB0 + (kt - 14) * TK);
            }
            mma_step(1);
            if (kt < KTILES - 1 || hasNext) {
                const int ns = slot ^ 1;
                mbar_wait(ctrl + ns * 8, (uint32_t)(((K + 1) >> 1) & 1));   // next stage written
                ldfrag(0, ns, 0);
            }
        }

        // ---- epilogue: exp(10*x), row sums + (off-diag) butterfly col sums ----
        __syncthreads();
        srow[t] = 0.0f;
        srow[t + 128] = 0.0f;
        __syncthreads();

        const int g  = lid >> 2;
        const int tg = lid & 3;

        float cs[8][2];
        #pragma unroll
        for (int nf = 0; nf < 8; nf++) { cs[nf][0] = 0.0f; cs[nf][1] = 0.0f; }

        #pragma unroll
        for (int mf = 0; mf < 4; mf++) {
            float rs0 = 0.0f, rs1 = 0.0f;
            const int gr0 = rowBase + wr * 64 + mf * 16 + g;
            const int gr1 = gr0 + 8;
            #pragma unroll
            for (int nf = 0; nf < 8; nf++) {
                float2 lo = __half22float2(*reinterpret_cast<__half2*>(&acc[mf][nf][0]));
                float2 hi = __half22float2(*reinterpret_cast<__half2*>(&acc[mf][nf][1]));
                float e0 = __expf(lo.x * 10.0f);
                float e1 = __expf(lo.y * 10.0f);
                float e2 = __expf(hi.x * 10.0f);
                float e3 = __expf(hi.y * 10.0f);
                if (diag) {
                    const int gc0 = colBase + wc * 64 + nf * 8 + 2 * tg;
                    const int gc1 = gc0 + 1;
                    if (gr0 == gc0) e0 = 0.0f;
                    if (gr0 == gc1) e1 = 0.0f;
                    if (gr1 == gc0) e2 = 0.0f;
                    if (gr1 == gc1) e3 = 0.0f;
                }
                rs0 += e0 + e1;
                rs1 += e2 + e3;
                cs[nf][0] += e0 + e2;
                cs[nf][1] += e1 + e3;
            }
            rs0 += __shfl_xor_sync(0xffffffffu, rs0, 1);
            rs0 += __shfl_xor_sync(0xffffffffu, rs0, 2);
            rs1 += __shfl_xor_sync(0xffffffffu, rs1, 1);
            rs1 += __shfl_xor_sync(0xffffffffu, rs1, 2);
            if (tg == 0) {
                atomicAdd(&srow[wr * 64 + mf * 16 + g],     rs0);
                atomicAdd(&srow[wr * 64 + mf * 16 + g + 8], rs1);
            }
        }
        if (!diag) {
            #pragma unroll
            for (int nf = 0; nf < 8; nf++) {
                #pragma unroll
                for (int h = 0; h < 2; h++) {
                    float v = cs[nf][h];
                    v += __shfl_xor_sync(0xffffffffu, v, 4);
                    v += __shfl_xor_sync(0xffffffffu, v, 8);
                    v += __shfl_xor_sync(0xffffffffu, v, 16);
                    if (g == 0)
                        atomicAdd(&scol[wc * 64 + nf * 8 + 2 * tg + h], v);
                }
            }
        }
        __syncthreads();
        atomicAdd(&g_rowsum[rowBase + t], srow[t]);
        if (!diag) atomicAdd(&g_rowsum[colBase + t], scol[t]);

        if (!hasNext) break;

        // reset accumulators and advance to the next tile
        #pragma unroll
        for (int mf = 0; mf < 4; mf++)
            #pragma unroll
            for (int nf = 0; nf < 8; nf++) { acc[mf][nf][0] = 0u; acc[mf][nf][1] = 0u; }
        tile = ntile;
        rowBase = nRow; colBase = nCol;
        pA0 = nA0; pB0 = nB0;
    }

    // ---- last CTA computes the loss ----
    __threadfence();
    __syncthreads();
    __shared__ int s_last;
    if (t == 0) s_last = (atomicAdd(&g_done, 1) == (int)gridDim.x - 1) ? 1 : 0;
    __syncthreads();
    if (s_last) {
        __threadfence();
        float acc2 = 0.0f;
        for (int i = t; i < N_CLASS; i += 128)
            acc2 += logf(g_rowsum[i] * (1.0f / (float)(N_CLASS - 1)));
        #pragma unroll
        for (int o = 16; o > 0; o >>= 1) acc2 += __shfl_xor_sync(0xffffffffu, acc2, o);
        if (lid == 0) srow[wid] = acc2;
        __syncthreads();
        if (t == 0)
            out[0] = (srow[0] + srow[1] + srow[2] + srow[3]) / (float)N_CLASS;
    }
}

// ============================================================================
extern "C" void kernel_launch(void* const* d_in, const int* in_sizes, int n_in,
                              void* d_out, int out_size)
{
    const float* features   = nullptr;
    const int*   labels     = nullptr;
    const float* prototypes = nullptr;
    for (int k = 0; k < n_in; k++) {
        if      (in_sizes[k] == BATCH)          labels     = (const int*)d_in[k];
        else if (in_sizes[k] == BATCH * FEAT)   features   = (const float*)d_in[k];
        else if (in_sizes[k] == N_CLASS * FEAT) prototypes = (const float*)d_in[k];
    }
    float* out = (float*)d_out;

    static bool attr_done = false;
    if (!attr_done) {
        cudaFuncSetAttribute(gemm_exp_kernel,
                             cudaFuncAttributeMaxDynamicSharedMemorySize, SMEM_TOTAL);
        attr_done = true;
    }

    ema_convert_kernel<<<N_CLASS, 256>>>(prototypes, features, labels);
    gemm_exp_kernel<<<PCTAS, 128, SMEM_TOTAL>>>(out);
    (void)out_size;
}

// round 14
// speedup vs baseline: 1.0895x; 1.0895x over previous
#include <cuda_runtime.h>
#include <cuda_fp16.h>
#include <cstdint>
#include <cstddef>

#define N_CLASS 8192
#define FEAT    1024
#define BATCH   1024

#define TM 128
#define TN 128
#define TK 64
#define KTILES (FEAT / TK)        // 16
#define A_BYTES (TM * 128)        // 16 KB (128 rows x 128B)
#define B_BYTES (TN * 128)        // 16 KB
#define STAGE_BYTES (A_BYTES + B_BYTES)   // 32 KB
#define CTRL_OFF (2 * STAGE_BYTES)        // 64 KB
#define SMEM_TOTAL (CTRL_OFF + 128)

#define NTILE (N_CLASS / TM)                  // 64
#define NTRI  (NTILE * (NTILE + 1) / 2)       // 2080 upper-triangle tiles
#define CAP 32

// ---------------- device scratch (no allocations allowed) ----------------
__device__ __half g_protos[(size_t)N_CLASS * FEAT];  // 16 MB fp16 protos
__device__ float  g_rowsum[N_CLASS];
__device__ int    g_done;

// ---------------- helpers ----------------
__device__ __forceinline__ uint32_t smem_u32(const void* p) {
    uint32_t a;
    asm("{ .reg .u64 t; cvta.to.shared.u64 t, %1; cvt.u32.u64 %0, t; }" : "=r"(a) : "l"(p));
    return a;
}
__device__ __forceinline__ void ldmatrix_x4(uint32_t& r0, uint32_t& r1,
                                            uint32_t& r2, uint32_t& r3, uint32_t addr) {
    asm volatile("ldmatrix.sync.aligned.m8n8.x4.shared.b16 {%0,%1,%2,%3}, [%4];"
                 : "=r"(r0), "=r"(r1), "=r"(r2), "=r"(r3) : "r"(addr));
}
__device__ __forceinline__ void mma_f16acc(uint32_t& c0, uint32_t& c1,
                                           uint32_t a0, uint32_t a1, uint32_t a2, uint32_t a3,
                                           uint32_t b0, uint32_t b1) {
    asm volatile(
        "mma.sync.aligned.m16n8k16.row.col.f16.f16.f16.f16 "
        "{%0,%1}, {%2,%3,%4,%5}, {%6,%7}, {%0,%1};"
        : "+r"(c0), "+r"(c1)
        : "r"(a0), "r"(a1), "r"(a2), "r"(a3), "r"(b0), "r"(b1));
}
__device__ __forceinline__ void mbar_init(uint32_t mbar, uint32_t cnt) {
    asm volatile("mbarrier.init.shared.b64 [%0], %1;" :: "r"(mbar), "r"(cnt) : "memory");
}
__device__ __forceinline__ void mbar_arrive(uint32_t mbar) {
    asm volatile("mbarrier.arrive.shared.b64 _, [%0];" :: "r"(mbar) : "memory");
}
__device__ __forceinline__ void cpasync_arrive(uint32_t mbar) {
    asm volatile("cp.async.mbarrier.arrive.noinc.shared.b64 [%0];" :: "r"(mbar) : "memory");
}
__device__ __forceinline__ void mbar_wait(uint32_t mbar, uint32_t parity) {
    asm volatile(
        "{\n\t.reg .pred P;\n\t"
        "W_%=:\n\t"
        "mbarrier.try_wait.parity.acquire.cta.shared::cta.b64 P, [%0], %1, 0x989680;\n\t"
        "@!P bra W_%=;\n\t}"
        :: "r"(mbar), "r"(parity) : "memory");
}

// ============================================================================
// Kernel 1: fused label-scan + EMA + fp32->fp16 convert. One block per class:
// scan labels for matches, run the sequential EMA chain if active, write fp16.
// Also zeroes g_rowsum (and g_done via block 0).
// ============================================================================
__global__ void __launch_bounds__(256) ema_convert_kernel(
    const float* __restrict__ protos,
    const float* __restrict__ feats,
    const int*   __restrict__ labels)
{
    const int c = blockIdx.x;
    const int t = threadIdx.x;

    __shared__ int   s_cnt;
    __shared__ int   s_idx[CAP];
    __shared__ float s_red[8];

    if (t == 0) s_cnt = 0;
    __syncthreads();

    // scan batch labels for this class (labels is 4KB -> L2 resident)
    #pragma unroll
    for (int i = t; i < BATCH; i += 256) {
        if (labels[i] == c) {
            int p = atomicAdd(&s_cnt, 1);
            if (p < CAP) s_idx[p] = i;
        }
    }
    __syncthreads();

    float4 r = reinterpret_cast<const float4*>(protos)[(size_t)c * (FEAT / 4) + t];

    const int cnt = min(s_cnt, CAP);
    if (cnt > 0) {
        if (t == 0) {  // order matters: insertion-sort the (tiny) match list
            for (int a = 1; a < cnt; a++) {
                int v = s_idx[a], b = a - 1;
                while (b >= 0 && s_idx[b] > v) { s_idx[b + 1] = s_idx[b]; b--; }
                s_idx[b + 1] = v;
            }
        }
        __syncthreads();
        for (int m = 0; m < cnt; m++) {
            const int i = s_idx[m];
            float4 f = reinterpret_cast<const float4*>(feats)[(size_t)i * (FEAT / 4) + t];
            r.x = r.x * 0.95f + 0.05f * f.x;
            r.y = r.y * 0.95f + 0.05f * f.y;
            r.z = r.z * 0.95f + 0.05f * f.z;
            r.w = r.w * 0.95f + 0.05f * f.w;
            float ss = r.x * r.x + r.y * r.y + r.z * r.z + r.w * r.w;
            #pragma unroll
            for (int o = 16; o > 0; o >>= 1) ss += __shfl_xor_sync(0xffffffffu, ss, o);
            if ((t & 31) == 0) s_red[t >> 5] = ss;
            __syncthreads();
            float tot = s_red[0] + s_red[1] + s_red[2] + s_red[3]
                      + s_red[4] + s_red[5] + s_red[6] + s_red[7];
            float inv = 1.0f / fmaxf(sqrtf(tot), 1e-12f);
            r.x *= inv; r.y *= inv; r.z *= inv; r.w *= inv;
            __syncthreads();
        }
    }

    __half2* dst = reinterpret_cast<__half2*>(g_protos + (size_t)c * FEAT + (size_t)t * 4);
    dst[0] = __floats2half2_rn(r.x, r.y);
    dst[1] = __floats2half2_rn(r.z, r.w);
    if (t == 0) {
        g_rowsum[c] = 0.0f;
        if (c == 0) g_done = 0;
    }
}

// ============================================================================
// Kernel 2: fused symmetric Gram GEMM (fp16) + exp + row/col sums + finalize.
// 2-slot mbarrier producer-consumer pipeline, 3 CTAs/SM (3 warps/SMSP),
// 4 warps of 64x64 (proven fastest configuration, R8/R11/R12).
// kt loop kept at unroll-2 to stay inside the 32KB I$ plateau.
// ============================================================================
__global__ void __launch_bounds__(128, 3) gemm_exp_kernel(float* __restrict__ out)
{
    // decode linear id -> upper-triangle (ti, tj), row-major
    const int id = blockIdx.x;
    int ti = (int)((2.0f * NTILE + 1.0f
                    - sqrtf((2.0f * NTILE + 1.0f) * (2.0f * NTILE + 1.0f) - 8.0f * id))
                   * 0.5f);
    while ((ti + 1) * NTILE - ((ti + 1) * ti) / 2 <= id) ti++;
    while (ti * NTILE - (ti * (ti - 1)) / 2 > id) ti--;
    const int tj = ti + (id - (ti * NTILE - (ti * (ti - 1)) / 2));

    const bool diag   = (ti == tj);
    const int rowBase = ti * TM;
    const int colBase = tj * TN;

    extern __shared__ __align__(1024) char smem[];
    const uint32_t sb   = smem_u32(smem);
    const uint32_t ctrl = sb + CTRL_OFF;   // wr[0],wr[1] at +0,+8 ; rd[0],rd[1] at +16,+24

    const int t   = threadIdx.x;          // 0..127
    const int wid = t >> 5;
    const int lid = t & 31;
    const int wr  = wid >> 1;
    const int wc  = wid & 1;

    const __half* __restrict__ P = g_protos;

    if (t == 0) {
        #pragma unroll
        for (int s = 0; s < 2; s++) { mbar_init(ctrl + s * 8, 128); mbar_init(ctrl + 16 + s * 8, 128); }
    }
    __syncthreads();

    // ---- async stage loader (16 x 16B per thread), completion via mbarrier ----
    const int kc = t & 7;
    const int r0 = t >> 3;
    const uint32_t dOffA = r0 * 128 + ((kc ^ (r0 & 7)) << 4);
    const __half* pA0 = P + (size_t)(rowBase + r0) * FEAT + kc * 8;
    const __half* pB0 = P + (size_t)(colBase + r0) * FEAT + kc * 8;

    auto load_stage = [&](int kt) {
        const int slot = kt & 1;
        const uint32_t dA = sb + slot * STAGE_BYTES + dOffA;
        const __half* sA = pA0 + kt * TK;
        const __half* sB = pB0 + kt * TK;
        #pragma unroll
        for (int q = 0; q < 8; q++) {
            asm volatile("cp.async.cg.shared.global [%0], [%1], 16;"
                         :: "r"(dA + q * 2048), "l"(sA + (size_t)q * 16 * FEAT));
            asm volatile("cp.async.cg.shared.global [%0], [%1], 16;"
                         :: "r"(dA + A_BYTES + q * 2048), "l"(sB + (size_t)q * 16 * FEAT));
        }
        cpasync_arrive(ctrl + slot * 8);
    };

    load_stage(0);
    load_stage(1);

    uint32_t acc[4][8][2];
    #pragma unroll
    for (int mf = 0; mf < 4; mf++)
        #pragma unroll
        for (int nf = 0; nf < 8; nf++) { acc[mf][nf][0] = 0u; acc[mf][nf][1] = 0u; }

    const int lmod16 = lid & 15;
    const int ldiv16 = lid >> 4;
    const int xsw    = lmod16 & 7;
    uint32_t aOff[4], bOff[4];
    #pragma unroll
    for (int mf = 0; mf < 4; mf++) aOff[mf] = (wr * 64 + mf * 16 + lmod16) * 128;
    #pragma unroll
    for (int np = 0; np < 4; np++) bOff[np] = (wc * 64 + np * 16 + lmod16) * 128;

    uint32_t a[2][4][4];
    uint32_t b[2][8][2];

    auto ldfrag = [&](int buf, int slot, int ks) {
        const uint32_t base = sb + slot * STAGE_BYTES;
        const uint32_t sw = (uint32_t)(((ks * 2 + ldiv16) ^ xsw) << 4);
        #pragma unroll
        for (int mf = 0; mf < 4; mf++)
            ldmatrix_x4(a[buf][mf][0], a[buf][mf][1], a[buf][mf][2], a[buf][mf][3],
                        base + aOff[mf] + sw);
        #pragma unroll
        for (int np = 0; np < 4; np++) {
            uint32_t q0, q1, q2, q3;
            ldmatrix_x4(q0, q1, q2, q3, base + A_BYTES + bOff[np] + sw);
            b[buf][np * 2 + 0][0] = q0; b[buf][np * 2 + 0][1] = q2;
            b[buf][np * 2 + 1][0] = q1; b[buf][np * 2 + 1][1] = q3;
        }
    };

    auto mma_step = [&](int buf) {
        #pragma unroll
        for (int mf = 0; mf < 4; mf++)
            #pragma unroll
            for (int nf = 0; nf < 8; nf++)
                mma_f16acc(acc[mf][nf][0], acc[mf][nf][1],
                           a[buf][mf][0], a[buf][mf][1], a[buf][mf][2], a[buf][mf][3],
                           b[buf][nf][0], b[buf][nf][1]);
    };

    mbar_wait(ctrl + 0, 0);       // stage 0 written
    ldfrag(0, 0, 0);

    #pragma unroll 2
    for (int kt = 0; kt < KTILES; kt++) {
        const int slot = kt & 1;
        ldfrag(1, slot, 1);
        mma_step(0);
        ldfrag(0, slot, 2);
        mma_step(1);
        ldfrag(1, slot, 3);
        mbar_arrive(ctrl + 16 + slot * 8);          // done reading this slot
        mma_step(0);
        if (kt <= KTILES - 3) {
            mbar_wait(ctrl + 16 + slot * 8, (uint32_t)((kt >> 1) & 1));   // all warps done
            load_stage(kt + 2);
        }
        mma_step(1);
        if (kt < KTILES - 1) {
            const int ns = slot ^ 1;
            mbar_wait(ctrl + ns * 8, (uint32_t)(((kt + 1) >> 1) & 1));    // next stage written
            ldfrag(0, ns, 0);
        }
    }

    // ---- epilogue: exp(10*x), row sums + (off-diag) butterfly column sums ----
    float* srow = reinterpret_cast<float*>(smem);        // [128]
    float* scol = srow + 128;                            // [128]
    __syncthreads();
    srow[t] = 0.0f;
    srow[t + 128] = 0.0f;
    __syncthreads();

    const int g  = lid >> 2;
    const int tg = lid & 3;

    float cs[8][2];
    #pragma unroll
    for (int nf = 0; nf < 8; nf++) { cs[nf][0] = 0.0f; cs[nf][1] = 0.0f; }

    #pragma unroll
    for (int mf = 0; mf < 4; mf++) {
        float rs0 = 0.0f, rs1 = 0.0f;
        const int gr0 = rowBase + wr * 64 + mf * 16 + g;
        const int gr1 = gr0 + 8;
        #pragma unroll
        for (int nf = 0; nf < 8; nf++) {
            float2 lo = __half22float2(*reinterpret_cast<__half2*>(&acc[mf][nf][0]));
            float2 hi = __half22float2(*reinterpret_cast<__half2*>(&acc[mf][nf][1]));
            float e0 = __expf(lo.x * 10.0f);
            float e1 = __expf(lo.y * 10.0f);
            float e2 = __expf(hi.x * 10.0f);
            float e3 = __expf(hi.y * 10.0f);
            if (diag) {
                const int gc0 = colBase + wc * 64 + nf * 8 + 2 * tg;
                const int gc1 = gc0 + 1;
                if (gr0 == gc0) e0 = 0.0f;
                if (gr0 == gc1) e1 = 0.0f;
                if (gr1 == gc0) e2 = 0.0f;
                if (gr1 == gc1) e3 = 0.0f;
            }
            rs0 += e0 + e1;
            rs1 += e2 + e3;
            cs[nf][0] += e0 + e2;
            cs[nf][1] += e1 + e3;
        }
        rs0 += __shfl_xor_sync(0xffffffffu, rs0, 1);
        rs0 += __shfl_xor_sync(0xffffffffu, rs0, 2);
        rs1 += __shfl_xor_sync(0xffffffffu, rs1, 1);
        rs1 += __shfl_xor_sync(0xffffffffu, rs1, 2);
        if (tg == 0) {
            atomicAdd(&srow[wr * 64 + mf * 16 + g],     rs0);
            atomicAdd(&srow[wr * 64 + mf * 16 + g + 8], rs1);
        }
    }
    if (!diag) {
        #pragma unroll
        for (int nf = 0; nf < 8; nf++) {
            #pragma unroll
            for (int h = 0; h < 2; h++) {
                float v = cs[nf][h];
                v += __shfl_xor_sync(0xffffffffu, v, 4);
                v += __shfl_xor_sync(0xffffffffu, v, 8);
                v += __shfl_xor_sync(0xffffffffu, v, 16);
                if (g == 0)
                    atomicAdd(&scol[wc * 64 + nf * 8 + 2 * tg + h], v);
            }
        }
    }
    __syncthreads();
    atomicAdd(&g_rowsum[rowBase + t], srow[t]);
    if (!diag) atomicAdd(&g_rowsum[colBase + t], scol[t]);

    // ---- last CTA computes the loss ----
    __threadfence();
    __syncthreads();
    __shared__ int s_last;
    if (t == 0) s_last = (atomicAdd(&g_done, 1) == NTRI - 1) ? 1 : 0;
    __syncthreads();
    if (s_last) {
        __threadfence();
        float acc2 = 0.0f;
        for (int i = t; i < N_CLASS; i += 128)
            acc2 += logf(g_rowsum[i] * (1.0f / (float)(N_CLASS - 1)));
        #pragma unroll
        for (int o = 16; o > 0; o >>= 1) acc2 += __shfl_xor_sync(0xffffffffu, acc2, o);
        if (lid == 0) srow[wid] = acc2;
        __syncthreads();
        if (t == 0)
            out[0] = (srow[0] + srow[1] + srow[2] + srow[3]) / (float)N_CLASS;
    }
}

// ============================================================================
extern "C" void kernel_launch(void* const* d_in, const int* in_sizes, int n_in,
                              void* d_out, int out_size)
{
    const float* features   = nullptr;
    const int*   labels     = nullptr;
    const float* prototypes = nullptr;
    for (int k = 0; k < n_in; k++) {
        if      (in_sizes[k] == BATCH)          labels     = (const int*)d_in[k];
        else if (in_sizes[k] == BATCH * FEAT)   features   = (const float*)d_in[k];
        else if (in_sizes[k] == N_CLASS * FEAT) prototypes = (const float*)d_in[k];
    }
    float* out = (float*)d_out;

    static bool attr_done = false;
    if (!attr_done) {
        cudaFuncSetAttribute(gemm_exp_kernel,
                             cudaFuncAttributeMaxDynamicSharedMemorySize, SMEM_TOTAL);
        attr_done = true;
    }

    ema_convert_kernel<<<N_CLASS, 256>>>(prototypes, features, labels);
    gemm_exp_kernel<<<NTRI, 128, SMEM_TOTAL>>>(out);
    (void)out_size;
}